// round 1
// baseline (speedup 1.0000x reference)
#include <cuda_runtime.h>
#include <cstddef>

#define N_NODES 8192
#define N_EDGES 262144
#define HID 128
#define FLATN (N_NODES * HID)   // 1048576

// ---------------- scratch (device globals; no allocation allowed) -----------
__device__ float g_h[FLATN];     // x@W buffer (reused for both layers)
__device__ float g_e1[FLATN];    // layer-1 output
__device__ float g_e2[FLATN];    // layer-2 output (= flat)
__device__ float g_deg[N_NODES];
__device__ float g_dinv[N_NODES];
__device__ float g_acc[HID];     // fc1 partial-sum accumulator

// ---------------- init: zero accumulators, deg = 1 (self-loop) --------------
__global__ void k_init() {
    int idx = blockIdx.x * blockDim.x + threadIdx.x;
    int stride = gridDim.x * blockDim.x;
    for (int i = idx; i < FLATN; i += stride) { g_e1[i] = 0.f; g_e2[i] = 0.f; }
    if (idx < N_NODES) g_deg[idx] = 1.0f;
    if (idx < HID) g_acc[idx] = 0.f;
}

// ---------------- degree accumulation over edge targets ---------------------
__global__ void k_deg(const int* __restrict__ col) {
    int e = blockIdx.x * blockDim.x + threadIdx.x;
    if (e < N_EDGES) atomicAdd(&g_deg[col[e]], 1.0f);
}

__global__ void k_dinv() {
    int i = blockIdx.x * blockDim.x + threadIdx.x;
    if (i < N_NODES) g_dinv[i] = rsqrtf(g_deg[i]);   // deg >= 1 (self-loops)
}

// ---------------- GEMM: out[8192,128] = A[8192,128] @ W[128,128] ------------
// 256 blocks x 32 rows, blockDim 128 (thread = output column).
// W staged in 64KB dynamic shared; A read via float4 __ldg broadcast.
__global__ void k_gemm(const float* __restrict__ A, const float* __restrict__ W,
                       float* __restrict__ out) {
    extern __shared__ float Ws[];   // 128*128 floats = 64 KB
    for (int i = threadIdx.x; i < HID * HID; i += blockDim.x) Ws[i] = W[i];
    __syncthreads();

    const int col = threadIdx.x;
    const int rbase = blockIdx.x * 32;

    for (int rg = 0; rg < 32; rg += 4) {
        const int r = rbase + rg;
        const float4* a0 = (const float4*)(A + (size_t)(r + 0) * HID);
        const float4* a1 = (const float4*)(A + (size_t)(r + 1) * HID);
        const float4* a2 = (const float4*)(A + (size_t)(r + 2) * HID);
        const float4* a3 = (const float4*)(A + (size_t)(r + 3) * HID);
        float acc0 = 0.f, acc1 = 0.f, acc2 = 0.f, acc3 = 0.f;
        #pragma unroll
        for (int k4 = 0; k4 < HID / 4; k4++) {
            float4 v0 = __ldg(a0 + k4);
            float4 v1 = __ldg(a1 + k4);
            float4 v2 = __ldg(a2 + k4);
            float4 v3 = __ldg(a3 + k4);
            float w0 = Ws[(4 * k4 + 0) * HID + col];
            float w1 = Ws[(4 * k4 + 1) * HID + col];
            float w2 = Ws[(4 * k4 + 2) * HID + col];
            float w3 = Ws[(4 * k4 + 3) * HID + col];
            acc0 += v0.x * w0 + v0.y * w1 + v0.z * w2 + v0.w * w3;
            acc1 += v1.x * w0 + v1.y * w1 + v1.z * w2 + v1.w * w3;
            acc2 += v2.x * w0 + v2.y * w1 + v2.z * w2 + v2.w * w3;
            acc3 += v3.x * w0 + v3.y * w1 + v3.z * w2 + v3.w * w3;
        }
        out[(size_t)(r + 0) * HID + col] = acc0;
        out[(size_t)(r + 1) * HID + col] = acc1;
        out[(size_t)(r + 2) * HID + col] = acc2;
        out[(size_t)(r + 3) * HID + col] = acc3;
    }
}

// ---------------- edge scatter: out[c] += dinv[r]*dinv[c] * h[r] ------------
// One warp per edge. Each lane: one float4 gather + one 16B vector reduction.
__global__ void k_scatter(const float* __restrict__ h,
                          const int* __restrict__ row,
                          const int* __restrict__ col,
                          float* __restrict__ out) {
    int gtid = blockIdx.x * blockDim.x + threadIdx.x;
    int e = gtid >> 5;
    int lane = gtid & 31;
    if (e >= N_EDGES) return;
    int r = __ldg(row + e);
    int c = __ldg(col + e);
    float n = g_dinv[r] * g_dinv[c];
    float4 v = __ldg((const float4*)(h + (size_t)r * HID) + lane);
    float* dst = out + (size_t)c * HID + lane * 4;
    asm volatile("red.global.add.v4.f32 [%0], {%1, %2, %3, %4};"
                 :: "l"(dst), "f"(v.x * n), "f"(v.y * n), "f"(v.z * n), "f"(v.w * n)
                 : "memory");
}

// ---------------- self-loop + bias (+ optional relu) ------------------------
// out[i,j] = act(out[i,j] + dinv[i]^2 * h[i,j] + b[j])
__global__ void k_self(const float* __restrict__ h, const float* __restrict__ b,
                       float* __restrict__ out, int do_relu) {
    int idx4 = blockIdx.x * blockDim.x + threadIdx.x;   // over FLATN/4
    if (idx4 >= FLATN / 4) return;
    int node = idx4 >> 5;            // 32 float4 per node
    float d = g_dinv[node];
    float nn = d * d;
    float4 hv = __ldg((const float4*)h + idx4);
    float4 ov = ((float4*)out)[idx4];
    float4 bv = __ldg((const float4*)b + (idx4 & 31));
    float x0 = ov.x + nn * hv.x + bv.x;
    float x1 = ov.y + nn * hv.y + bv.y;
    float x2 = ov.z + nn * hv.z + bv.z;
    float x3 = ov.w + nn * hv.w + bv.w;
    if (do_relu) {
        x0 = fmaxf(x0, 0.f); x1 = fmaxf(x1, 0.f);
        x2 = fmaxf(x2, 0.f); x3 = fmaxf(x3, 0.f);
    }
    ((float4*)out)[idx4] = make_float4(x0, x1, x2, x3);
}

// ---------------- fc1 partial: g_acc[j] += sum_i flat[i] * W[i,j] -----------
// 1024 blocks x 1024 rows each; blockDim 128 (thread = column).
__global__ void k_fc1(const float* __restrict__ flat, const float* __restrict__ W) {
    __shared__ float fs[128];
    const int col = threadIdx.x;
    const size_t base = (size_t)blockIdx.x * 1024;
    float s = 0.f;
    for (int t = 0; t < 1024; t += 128) {
        fs[col] = flat[base + t + col];
        __syncthreads();
        const float* Wp = W + (base + t) * HID + col;
        #pragma unroll 8
        for (int i = 0; i < 128; i++) {
            s += fs[i] * Wp[(size_t)i * HID];
        }
        __syncthreads();
    }
    atomicAdd(&g_acc[col], s);
}

// ---------------- tail: relu(fc1) -> fc2+relu -> fc3 -> scalar --------------
__global__ void k_tail(const float* __restrict__ fc1_b,
                       const float* __restrict__ fc2_w,
                       const float* __restrict__ fc2_b,
                       const float* __restrict__ fc3_w,
                       const float* __restrict__ fc3_b,
                       float* __restrict__ out) {
    __shared__ float h1[HID];
    __shared__ float red[4];
    int tid = threadIdx.x;
    h1[tid] = fmaxf(g_acc[tid] + fc1_b[tid], 0.f);
    __syncthreads();
    float s = 0.f;
    #pragma unroll 8
    for (int k = 0; k < HID; k++) s += h1[k] * fc2_w[k * HID + tid];
    float h2 = fmaxf(s + fc2_b[tid], 0.f);
    float p = h2 * fc3_w[tid];
    #pragma unroll
    for (int o = 16; o; o >>= 1) p += __shfl_xor_sync(0xFFFFFFFFu, p, o);
    if ((tid & 31) == 0) red[tid >> 5] = p;
    __syncthreads();
    if (tid == 0) out[0] = red[0] + red[1] + red[2] + red[3] + fc3_b[0];
}

// ---------------- launch ----------------------------------------------------
extern "C" void kernel_launch(void* const* d_in, const int* in_sizes, int n_in,
                              void* d_out, int out_size) {
    const float* x      = (const float*)d_in[0];
    const int*   ei     = (const int*)d_in[1];     // [2, N_EDGES] row-major
    const float* W1     = (const float*)d_in[2];
    const float* b1     = (const float*)d_in[3];
    const float* W2     = (const float*)d_in[4];
    const float* b2     = (const float*)d_in[5];
    const float* fc1_w  = (const float*)d_in[6];
    const float* fc1_b  = (const float*)d_in[7];
    const float* fc2_w  = (const float*)d_in[8];
    const float* fc2_b  = (const float*)d_in[9];
    const float* fc3_w  = (const float*)d_in[10];
    const float* fc3_b  = (const float*)d_in[11];
    float* out = (float*)d_out;

    const int* row = ei;               // sources
    const int* colv = ei + N_EDGES;    // targets

    // Get raw device pointers to scratch globals
    float *p_h, *p_e1, *p_e2;
    cudaGetSymbolAddress((void**)&p_h,  g_h);
    cudaGetSymbolAddress((void**)&p_e1, g_e1);
    cudaGetSymbolAddress((void**)&p_e2, g_e2);

    cudaFuncSetAttribute(k_gemm, cudaFuncAttributeMaxDynamicSharedMemorySize, 65536);

    k_init<<<1024, 256>>>();
    k_deg<<<N_EDGES / 256, 256>>>(colv);
    k_dinv<<<N_NODES / 256, 256>>>();

    // Layer 1
    k_gemm<<<256, 128, 65536>>>(x, W1, p_h);
    k_scatter<<<(N_EDGES * 32) / 256, 256>>>(p_h, row, colv, p_e1);
    k_self<<<(FLATN / 4) / 256, 256>>>(p_h, b1, p_e1, 1);

    // Layer 2
    k_gemm<<<256, 128, 65536>>>(p_e1, W2, p_h);
    k_scatter<<<(N_EDGES * 32) / 256, 256>>>(p_h, row, colv, p_e2);
    k_self<<<(FLATN / 4) / 256, 256>>>(p_h, b2, p_e2, 0);

    // MLP head
    k_fc1<<<1024, 128>>>(p_e2, fc1_w);
    k_tail<<<1, 128>>>(fc1_b, fc2_w, fc2_b, fc3_w, fc3_b, out);
}

// round 2
// speedup vs baseline: 1.7208x; 1.7208x over previous
#include <cuda_runtime.h>
#include <cstddef>

#define N_NODES 8192
#define N_EDGES 262144
#define HID 128
#define FLATN (N_NODES * HID)   // 1048576

// ---------------- scratch (device globals; no allocation allowed) -----------
__device__ float g_h[FLATN];     // x@W buffer (reused for both layers)
__device__ float g_e1[FLATN];    // layer-1 output
__device__ float g_e2[FLATN];    // layer-2 output (= flat)
__device__ float g_deg[N_NODES];
__device__ float g_dinv[N_NODES];
__device__ float g_acc[HID];     // fc1 partial-sum accumulator

// ---------------- init: zero accumulators, deg = 1 (self-loop) --------------
__global__ void k_init() {
    int idx = blockIdx.x * blockDim.x + threadIdx.x;
    int stride = gridDim.x * blockDim.x;
    float4 z = make_float4(0.f, 0.f, 0.f, 0.f);
    for (int i = idx; i < FLATN / 4; i += stride) {
        ((float4*)g_e1)[i] = z;
        ((float4*)g_e2)[i] = z;
    }
    if (idx < N_NODES) g_deg[idx] = 1.0f;
    if (idx < HID) g_acc[idx] = 0.f;
}

// ---------------- degree accumulation over edge targets ---------------------
__global__ void k_deg(const int* __restrict__ col) {
    int e = blockIdx.x * blockDim.x + threadIdx.x;
    if (e < N_EDGES) atomicAdd(&g_deg[col[e]], 1.0f);
}

__global__ void k_dinv() {
    int i = blockIdx.x * blockDim.x + threadIdx.x;
    if (i < N_NODES) g_dinv[i] = rsqrtf(g_deg[i]);   // deg >= 1 (self-loops)
}

// ---------------- GEMM: out[8192,128] = A[8192,128] @ W[128,128] ------------
// Register-tiled: BM=32 rows/block, 256 threads, 4x4 tile per thread.
// W (128x132 padded) + A tile (32x132) in dynamic smem. 256 blocks.
#define GBM 32
#define WPITCH 132
__global__ void __launch_bounds__(256, 2) k_gemm(const float* __restrict__ A,
                                                 const float* __restrict__ W,
                                                 float* __restrict__ out) {
    extern __shared__ float smem[];
    float* Ws = smem;                       // [128][WPITCH]
    float* As = smem + 128 * WPITCH;        // [GBM][WPITCH]

    const int tid = threadIdx.x;

    // Load W: 4096 float4, 16 per thread. Row k, float4-col c4.
    #pragma unroll
    for (int i = tid; i < 128 * 32; i += 256) {
        int k = i >> 5;
        int c4 = i & 31;
        float4 v = __ldg((const float4*)(W + k * HID) + c4);
        *(float4*)&Ws[k * WPITCH + c4 * 4] = v;
    }
    // Load A tile: 32x128 = 1024 float4, 4 per thread.
    const float* Ab = A + (size_t)blockIdx.x * GBM * HID;
    #pragma unroll
    for (int i = tid; i < GBM * 32; i += 256) {
        int r = i >> 5;
        int c4 = i & 31;
        *(float4*)&As[r * WPITCH + c4 * 4] = __ldg((const float4*)(Ab + r * HID) + c4);
    }
    __syncthreads();

    const int tx = tid & 31;    // col group: cols tx*4..tx*4+3 (warp-contiguous)
    const int ty = tid >> 5;    // row group: rows ty*4..ty*4+3 (uniform per warp)

    float acc[4][4];
    #pragma unroll
    for (int i = 0; i < 4; i++)
        #pragma unroll
        for (int j = 0; j < 4; j++) acc[i][j] = 0.f;

    const float* As0 = &As[(ty * 4 + 0) * WPITCH];
    const float* As1 = &As[(ty * 4 + 1) * WPITCH];
    const float* As2 = &As[(ty * 4 + 2) * WPITCH];
    const float* As3 = &As[(ty * 4 + 3) * WPITCH];

    #pragma unroll 8
    for (int k = 0; k < 128; k++) {
        float4 wv = *(const float4*)&Ws[k * WPITCH + tx * 4];
        float a0 = As0[k], a1 = As1[k], a2 = As2[k], a3 = As3[k];
        acc[0][0] += a0 * wv.x; acc[0][1] += a0 * wv.y; acc[0][2] += a0 * wv.z; acc[0][3] += a0 * wv.w;
        acc[1][0] += a1 * wv.x; acc[1][1] += a1 * wv.y; acc[1][2] += a1 * wv.z; acc[1][3] += a1 * wv.w;
        acc[2][0] += a2 * wv.x; acc[2][1] += a2 * wv.y; acc[2][2] += a2 * wv.z; acc[2][3] += a2 * wv.w;
        acc[3][0] += a3 * wv.x; acc[3][1] += a3 * wv.y; acc[3][2] += a3 * wv.z; acc[3][3] += a3 * wv.w;
    }

    #pragma unroll
    for (int i = 0; i < 4; i++) {
        float4 v = make_float4(acc[i][0], acc[i][1], acc[i][2], acc[i][3]);
        *(float4*)(out + (size_t)(blockIdx.x * GBM + ty * 4 + i) * HID + tx * 4) = v;
    }
}
#define GEMM_SMEM ((128 * WPITCH + GBM * WPITCH) * 4)

// ---------------- edge scatter: out[c] += dinv[r]*dinv[c] * h[r] ------------
// One warp per edge. Each lane: one float4 gather + one 16B vector reduction.
__global__ void k_scatter(const float* __restrict__ h,
                          const int* __restrict__ row,
                          const int* __restrict__ col,
                          float* __restrict__ out) {
    int gtid = blockIdx.x * blockDim.x + threadIdx.x;
    int e = gtid >> 5;
    int lane = gtid & 31;
    if (e >= N_EDGES) return;
    int r = __ldg(row + e);
    int c = __ldg(col + e);
    float n = g_dinv[r] * g_dinv[c];
    float4 v = __ldg((const float4*)(h + (size_t)r * HID) + lane);
    float* dst = out + (size_t)c * HID + lane * 4;
    asm volatile("red.global.add.v4.f32 [%0], {%1, %2, %3, %4};"
                 :: "l"(dst), "f"(v.x * n), "f"(v.y * n), "f"(v.z * n), "f"(v.w * n)
                 : "memory");
}

// ---------------- self-loop + bias (+ optional relu) ------------------------
// out[i,j] = act(out[i,j] + dinv[i]^2 * h[i,j] + b[j])
__global__ void k_self(const float* __restrict__ h, const float* __restrict__ b,
                       float* __restrict__ out, int do_relu) {
    int idx4 = blockIdx.x * blockDim.x + threadIdx.x;   // over FLATN/4
    if (idx4 >= FLATN / 4) return;
    int node = idx4 >> 5;            // 32 float4 per node
    float d = g_dinv[node];
    float nn = d * d;
    float4 hv = __ldg((const float4*)h + idx4);
    float4 ov = ((float4*)out)[idx4];
    float4 bv = __ldg((const float4*)b + (idx4 & 31));
    float x0 = ov.x + nn * hv.x + bv.x;
    float x1 = ov.y + nn * hv.y + bv.y;
    float x2 = ov.z + nn * hv.z + bv.z;
    float x3 = ov.w + nn * hv.w + bv.w;
    if (do_relu) {
        x0 = fmaxf(x0, 0.f); x1 = fmaxf(x1, 0.f);
        x2 = fmaxf(x2, 0.f); x3 = fmaxf(x3, 0.f);
    }
    ((float4*)out)[idx4] = make_float4(x0, x1, x2, x3);
}

// ---------------- fc1 partial: g_acc[j] += sum_i flat[i] * W[i,j] -----------
// 1 warp per row: lane loads float4 of W row, FMA by flat[row].
// 1024 blocks x 256 threads (8 warps); each block covers 1024 rows.
__global__ void __launch_bounds__(256) k_fc1(const float* __restrict__ flat,
                                             const float* __restrict__ W) {
    const int tid = threadIdx.x;
    const int lane = tid & 31;
    const int warp = tid >> 5;     // 0..7
    const size_t base = (size_t)blockIdx.x * 1024;

    float4 acc = make_float4(0.f, 0.f, 0.f, 0.f);
    #pragma unroll 4
    for (int r = warp; r < 1024; r += 8) {
        size_t row = base + r;
        float f = __ldg(flat + row);
        float4 w = __ldg((const float4*)(W + row * HID) + lane);
        acc.x += f * w.x; acc.y += f * w.y; acc.z += f * w.z; acc.w += f * w.w;
    }

    __shared__ float4 red[8][32];
    red[warp][lane] = acc;
    __syncthreads();
    if (warp == 0) {
        float4 s = red[0][lane];
        #pragma unroll
        for (int w = 1; w < 8; w++) {
            float4 t = red[w][lane];
            s.x += t.x; s.y += t.y; s.z += t.z; s.w += t.w;
        }
        float* dst = &g_acc[lane * 4];
        asm volatile("red.global.add.v4.f32 [%0], {%1, %2, %3, %4};"
                     :: "l"(dst), "f"(s.x), "f"(s.y), "f"(s.z), "f"(s.w)
                     : "memory");
    }
}

// ---------------- tail: relu(fc1) -> fc2+relu -> fc3 -> scalar --------------
__global__ void k_tail(const float* __restrict__ fc1_b,
                       const float* __restrict__ fc2_w,
                       const float* __restrict__ fc2_b,
                       const float* __restrict__ fc3_w,
                       const float* __restrict__ fc3_b,
                       float* __restrict__ out) {
    __shared__ float h1[HID];
    __shared__ float red[4];
    int tid = threadIdx.x;
    h1[tid] = fmaxf(g_acc[tid] + fc1_b[tid], 0.f);
    __syncthreads();
    float s = 0.f;
    #pragma unroll 8
    for (int k = 0; k < HID; k++) s += h1[k] * fc2_w[k * HID + tid];
    float h2 = fmaxf(s + fc2_b[tid], 0.f);
    float p = h2 * fc3_w[tid];
    #pragma unroll
    for (int o = 16; o; o >>= 1) p += __shfl_xor_sync(0xFFFFFFFFu, p, o);
    if ((tid & 31) == 0) red[tid >> 5] = p;
    __syncthreads();
    if (tid == 0) out[0] = red[0] + red[1] + red[2] + red[3] + fc3_b[0];
}

// ---------------- launch ----------------------------------------------------
extern "C" void kernel_launch(void* const* d_in, const int* in_sizes, int n_in,
                              void* d_out, int out_size) {
    const float* x      = (const float*)d_in[0];
    const int*   ei     = (const int*)d_in[1];     // [2, N_EDGES] row-major
    const float* W1     = (const float*)d_in[2];
    const float* b1     = (const float*)d_in[3];
    const float* W2     = (const float*)d_in[4];
    const float* b2     = (const float*)d_in[5];
    const float* fc1_w  = (const float*)d_in[6];
    const float* fc1_b  = (const float*)d_in[7];
    const float* fc2_w  = (const float*)d_in[8];
    const float* fc2_b  = (const float*)d_in[9];
    const float* fc3_w  = (const float*)d_in[10];
    const float* fc3_b  = (const float*)d_in[11];
    float* out = (float*)d_out;

    const int* row = ei;               // sources
    const int* colv = ei + N_EDGES;    // targets

    float *p_h, *p_e1, *p_e2;
    cudaGetSymbolAddress((void**)&p_h,  g_h);
    cudaGetSymbolAddress((void**)&p_e1, g_e1);
    cudaGetSymbolAddress((void**)&p_e2, g_e2);

    cudaFuncSetAttribute(k_gemm, cudaFuncAttributeMaxDynamicSharedMemorySize, GEMM_SMEM);

    k_init<<<1024, 256>>>();
    k_deg<<<N_EDGES / 256, 256>>>(colv);
    k_dinv<<<N_NODES / 256, 256>>>();

    // Layer 1
    k_gemm<<<N_NODES / GBM, 256, GEMM_SMEM>>>(x, W1, p_h);
    k_scatter<<<(N_EDGES * 32) / 256, 256>>>(p_h, row, colv, p_e1);
    k_self<<<(FLATN / 4) / 256, 256>>>(p_h, b1, p_e1, 1);

    // Layer 2
    k_gemm<<<N_NODES / GBM, 256, GEMM_SMEM>>>(p_e1, W2, p_h);
    k_scatter<<<(N_EDGES * 32) / 256, 256>>>(p_h, row, colv, p_e2);
    k_self<<<(FLATN / 4) / 256, 256>>>(p_h, b2, p_e2, 0);

    // MLP head
    k_fc1<<<1024, 256>>>(p_e2, fc1_w);
    k_tail<<<1, 128>>>(fc1_b, fc2_w, fc2_b, fc3_w, fc3_b, out);
}

// round 3
// speedup vs baseline: 1.7856x; 1.0377x over previous
#include <cuda_runtime.h>
#include <cstddef>

#define N_NODES 8192
#define N_EDGES 262144
#define HID 128
#define FLATN (N_NODES * HID)   // 1048576

// ---------------- scratch (device globals) ----------------------------------
__device__ float g_h[FLATN];       // x@W buffer (reused for both layers)
__device__ float g_e1[FLATN];      // layer-1 output
__device__ int   g_degi[N_NODES];  // int degree histogram (edges only)
__device__ float g_dinv[N_NODES];
__device__ int   g_rowptr[N_NODES + 1];
__device__ int   g_cursor[N_NODES];
__device__ int   g_src[N_EDGES];   // CSR: source node per (target-sorted) edge
__device__ float g_acc[HID];       // fc1 partial-sum accumulator

// ---------------- prep: zero degree histogram -------------------------------
__global__ void k_prep() {
    int i = blockIdx.x * blockDim.x + threadIdx.x;
    if (i < N_NODES) g_degi[i] = 0;
}

// ---------------- degree histogram over edge targets ------------------------
__global__ void k_deg(const int* __restrict__ col) {
    int e = blockIdx.x * blockDim.x + threadIdx.x;
    if (e < N_EDGES) atomicAdd(&g_degi[col[e]], 1);
}

// ---------------- single-block scan: rowptr, cursor, dinv, acc=0 ------------
// 1024 threads, 8 elements each.
__global__ void __launch_bounds__(1024) k_scan() {
    const int t = threadIdx.x;
    int v[8];
    int s = 0;
    #pragma unroll
    for (int i = 0; i < 8; i++) {
        int d = g_degi[t * 8 + i];
        v[i] = s;          // local exclusive prefix
        s += d;
    }
    // warp-level inclusive scan of s
    int lane = t & 31, warp = t >> 5;
    int inc = s;
    #pragma unroll
    for (int o = 1; o < 32; o <<= 1) {
        int n = __shfl_up_sync(0xFFFFFFFFu, inc, o);
        if (lane >= o) inc += n;
    }
    __shared__ int wsum[32];
    if (lane == 31) wsum[warp] = inc;
    __syncthreads();
    if (warp == 0) {
        int w = wsum[lane];
        #pragma unroll
        for (int o = 1; o < 32; o <<= 1) {
            int n = __shfl_up_sync(0xFFFFFFFFu, w, o);
            if (lane >= o) w += n;
        }
        wsum[lane] = w;
    }
    __syncthreads();
    int base = inc - s + (warp ? wsum[warp - 1] : 0);   // exclusive prefix for thread
    #pragma unroll
    for (int i = 0; i < 8; i++) {
        int p = base + v[i];
        g_rowptr[t * 8 + i] = p;
        g_cursor[t * 8 + i] = p;
    }
    if (t == 1023) g_rowptr[N_NODES] = N_EDGES;
    // dinv (self-loop adds 1 to degree)
    #pragma unroll
    for (int i = 0; i < 8; i++) {
        int n = t * 8 + i;
        g_dinv[n] = rsqrtf((float)(g_degi[n] + 1));
    }
    if (t < HID) g_acc[t] = 0.f;
}

// ---------------- CSR fill ---------------------------------------------------
__global__ void k_fill(const int* __restrict__ row, const int* __restrict__ col) {
    int e = blockIdx.x * blockDim.x + threadIdx.x;
    if (e >= N_EDGES) return;
    int c = col[e];
    int pos = atomicAdd(&g_cursor[c], 1);
    g_src[pos] = row[e];
}

// ---------------- GEMM: out[8192,128] = A[8192,128] @ W[128,128] ------------
#define GBM 32
#define WPITCH 132
__global__ void __launch_bounds__(256, 2) k_gemm(const float* __restrict__ A,
                                                 const float* __restrict__ W,
                                                 float* __restrict__ out) {
    extern __shared__ float smem[];
    float* Ws = smem;                       // [128][WPITCH]
    float* As = smem + 128 * WPITCH;        // [GBM][WPITCH]
    const int tid = threadIdx.x;

    #pragma unroll
    for (int i = tid; i < 128 * 32; i += 256) {
        int k = i >> 5, c4 = i & 31;
        *(float4*)&Ws[k * WPITCH + c4 * 4] = __ldg((const float4*)(W + k * HID) + c4);
    }
    const float* Ab = A + (size_t)blockIdx.x * GBM * HID;
    #pragma unroll
    for (int i = tid; i < GBM * 32; i += 256) {
        int r = i >> 5, c4 = i & 31;
        *(float4*)&As[r * WPITCH + c4 * 4] = __ldg((const float4*)(Ab + r * HID) + c4);
    }
    __syncthreads();

    const int tx = tid & 31;
    const int ty = tid >> 5;
    float acc[4][4];
    #pragma unroll
    for (int i = 0; i < 4; i++)
        #pragma unroll
        for (int j = 0; j < 4; j++) acc[i][j] = 0.f;

    const float* As0 = &As[(ty * 4 + 0) * WPITCH];
    const float* As1 = &As[(ty * 4 + 1) * WPITCH];
    const float* As2 = &As[(ty * 4 + 2) * WPITCH];
    const float* As3 = &As[(ty * 4 + 3) * WPITCH];

    #pragma unroll 8
    for (int k = 0; k < 128; k++) {
        float4 wv = *(const float4*)&Ws[k * WPITCH + tx * 4];
        float a0 = As0[k], a1 = As1[k], a2 = As2[k], a3 = As3[k];
        acc[0][0] += a0 * wv.x; acc[0][1] += a0 * wv.y; acc[0][2] += a0 * wv.z; acc[0][3] += a0 * wv.w;
        acc[1][0] += a1 * wv.x; acc[1][1] += a1 * wv.y; acc[1][2] += a1 * wv.z; acc[1][3] += a1 * wv.w;
        acc[2][0] += a2 * wv.x; acc[2][1] += a2 * wv.y; acc[2][2] += a2 * wv.z; acc[2][3] += a2 * wv.w;
        acc[3][0] += a3 * wv.x; acc[3][1] += a3 * wv.y; acc[3][2] += a3 * wv.z; acc[3][3] += a3 * wv.w;
    }
    #pragma unroll
    for (int i = 0; i < 4; i++) {
        float4 v = make_float4(acc[i][0], acc[i][1], acc[i][2], acc[i][3]);
        *(float4*)(out + (size_t)(blockIdx.x * GBM + ty * 4 + i) * HID + tx * 4) = v;
    }
}
#define GEMM_SMEM ((128 * WPITCH + GBM * WPITCH) * 4)

// ---------------- gather (layer 1): e1[c] = relu(sum + self + bias) ---------
// One warp per target node; CSR neighbor list; register accumulation.
__global__ void __launch_bounds__(256) k_gather(const float* __restrict__ h,
                                                const float* __restrict__ b,
                                                float* __restrict__ out) {
    const int gtid = blockIdx.x * blockDim.x + threadIdx.x;
    const int node = gtid >> 5;
    const int lane = gtid & 31;
    if (node >= N_NODES) return;
    const int start = g_rowptr[node];
    const int end   = g_rowptr[node + 1];
    const float dc  = g_dinv[node];

    float4 acc = make_float4(0.f, 0.f, 0.f, 0.f);
    for (int j = start; j < end; j += 32) {
        int n = min(32, end - j);
        int s = 0; float dv = 0.f;
        if (lane < n) { s = __ldg(g_src + j + lane); dv = g_dinv[s]; }
        for (int k = 0; k < n; k++) {
            int src   = __shfl_sync(0xFFFFFFFFu, s, k);
            float nrm = __shfl_sync(0xFFFFFFFFu, dv, k) * dc;
            float4 v  = __ldg((const float4*)(h + (size_t)src * HID) + lane);
            acc.x += nrm * v.x; acc.y += nrm * v.y; acc.z += nrm * v.z; acc.w += nrm * v.w;
        }
    }
    float nn = dc * dc;
    float4 hv = __ldg((const float4*)(h + (size_t)node * HID) + lane);
    float4 bv = __ldg((const float4*)b + lane);
    acc.x = fmaxf(acc.x + nn * hv.x + bv.x, 0.f);
    acc.y = fmaxf(acc.y + nn * hv.y + bv.y, 0.f);
    acc.z = fmaxf(acc.z + nn * hv.z + bv.z, 0.f);
    acc.w = fmaxf(acc.w + nn * hv.w + bv.w, 0.f);
    *(float4*)(out + (size_t)node * HID + lane * 4) = acc;
}

// ---------------- gather (layer 2) fused with fc1 ---------------------------
// Phase 1: warp computes flat[node][:] (gather + self + bias, no relu) to smem.
// Phase 2: warp streams node's 64KB slab of fc1_w, rank-1 accumulates,
//          one red.v4 into g_acc per warp.
__global__ void __launch_bounds__(256) k_gather_fc1(const float* __restrict__ h,
                                                    const float* __restrict__ b,
                                                    const float* __restrict__ fc1_w) {
    __shared__ float fs[8][HID];
    const int gtid = blockIdx.x * blockDim.x + threadIdx.x;
    const int node = gtid >> 5;
    const int lane = gtid & 31;
    const int warp = (threadIdx.x) >> 5;
    if (node >= N_NODES) return;
    const int start = g_rowptr[node];
    const int end   = g_rowptr[node + 1];
    const float dc  = g_dinv[node];

    float4 acc = make_float4(0.f, 0.f, 0.f, 0.f);
    for (int j = start; j < end; j += 32) {
        int n = min(32, end - j);
        int s = 0; float dv = 0.f;
        if (lane < n) { s = __ldg(g_src + j + lane); dv = g_dinv[s]; }
        for (int k = 0; k < n; k++) {
            int src   = __shfl_sync(0xFFFFFFFFu, s, k);
            float nrm = __shfl_sync(0xFFFFFFFFu, dv, k) * dc;
            float4 v  = __ldg((const float4*)(h + (size_t)src * HID) + lane);
            acc.x += nrm * v.x; acc.y += nrm * v.y; acc.z += nrm * v.z; acc.w += nrm * v.w;
        }
    }
    float nn = dc * dc;
    float4 hv = __ldg((const float4*)(h + (size_t)node * HID) + lane);
    float4 bv = __ldg((const float4*)b + lane);
    acc.x += nn * hv.x + bv.x;
    acc.y += nn * hv.y + bv.y;
    acc.z += nn * hv.z + bv.z;
    acc.w += nn * hv.w + bv.w;
    *(float4*)&fs[warp][lane * 4] = acc;
    __syncwarp();

    // Phase 2: fc1 partial for this node's 128 flat values
    const float* Wb = fc1_w + (size_t)node * HID * HID;
    float4 p = make_float4(0.f, 0.f, 0.f, 0.f);
    #pragma unroll 8
    for (int j = 0; j < HID; j++) {
        float fj = fs[warp][j];
        float4 w = __ldg((const float4*)(Wb + (size_t)j * HID) + lane);
        p.x += fj * w.x; p.y += fj * w.y; p.z += fj * w.z; p.w += fj * w.w;
    }
    float* dst = &g_acc[lane * 4];
    asm volatile("red.global.add.v4.f32 [%0], {%1, %2, %3, %4};"
                 :: "l"(dst), "f"(p.x), "f"(p.y), "f"(p.z), "f"(p.w)
                 : "memory");
}

// ---------------- tail: relu(fc1) -> fc2+relu -> fc3 -> scalar --------------
__global__ void k_tail(const float* __restrict__ fc1_b,
                       const float* __restrict__ fc2_w,
                       const float* __restrict__ fc2_b,
                       const float* __restrict__ fc3_w,
                       const float* __restrict__ fc3_b,
                       float* __restrict__ out) {
    __shared__ float h1[HID];
    __shared__ float red[4];
    int tid = threadIdx.x;
    h1[tid] = fmaxf(g_acc[tid] + fc1_b[tid], 0.f);
    __syncthreads();
    float s = 0.f;
    #pragma unroll 8
    for (int k = 0; k < HID; k++) s += h1[k] * fc2_w[k * HID + tid];
    float h2 = fmaxf(s + fc2_b[tid], 0.f);
    float p = h2 * fc3_w[tid];
    #pragma unroll
    for (int o = 16; o; o >>= 1) p += __shfl_xor_sync(0xFFFFFFFFu, p, o);
    if ((tid & 31) == 0) red[tid >> 5] = p;
    __syncthreads();
    if (tid == 0) out[0] = red[0] + red[1] + red[2] + red[3] + fc3_b[0];
}

// ---------------- launch ----------------------------------------------------
extern "C" void kernel_launch(void* const* d_in, const int* in_sizes, int n_in,
                              void* d_out, int out_size) {
    const float* x      = (const float*)d_in[0];
    const int*   ei     = (const int*)d_in[1];     // [2, N_EDGES] row-major
    const float* W1     = (const float*)d_in[2];
    const float* b1     = (const float*)d_in[3];
    const float* W2     = (const float*)d_in[4];
    const float* b2     = (const float*)d_in[5];
    const float* fc1_w  = (const float*)d_in[6];
    const float* fc1_b  = (const float*)d_in[7];
    const float* fc2_w  = (const float*)d_in[8];
    const float* fc2_b  = (const float*)d_in[9];
    const float* fc3_w  = (const float*)d_in[10];
    const float* fc3_b  = (const float*)d_in[11];
    float* out = (float*)d_out;

    const int* row = ei;               // sources
    const int* colv = ei + N_EDGES;    // targets

    float *p_h, *p_e1;
    cudaGetSymbolAddress((void**)&p_h,  g_h);
    cudaGetSymbolAddress((void**)&p_e1, g_e1);

    cudaFuncSetAttribute(k_gemm, cudaFuncAttributeMaxDynamicSharedMemorySize, GEMM_SMEM);

    // Graph preprocessing: CSR by target + dinv
    k_prep<<<N_NODES / 256, 256>>>();
    k_deg<<<N_EDGES / 256, 256>>>(colv);
    k_scan<<<1, 1024>>>();
    k_fill<<<N_EDGES / 256, 256>>>(row, colv);

    // Layer 1
    k_gemm<<<N_NODES / GBM, 256, GEMM_SMEM>>>(x, W1, p_h);
    k_gather<<<(N_NODES * 32) / 256, 256>>>(p_h, b1, p_e1);

    // Layer 2 + fc1 fused
    k_gemm<<<N_NODES / GBM, 256, GEMM_SMEM>>>(p_e1, W2, p_h);
    k_gather_fc1<<<(N_NODES * 32) / 256, 256>>>(p_h, b2, fc1_w);

    // MLP tail
    k_tail<<<1, 128>>>(fc1_b, fc2_w, fc2_b, fc3_w, fc3_b, out);
}

// round 4
// speedup vs baseline: 1.8596x; 1.0414x over previous
#include <cuda_runtime.h>
#include <cstddef>

#define N_NODES 8192
#define N_EDGES 262144
#define HID 128
#define FLATN (N_NODES * HID)   // 1048576

// ---------------- scratch (device globals) ----------------------------------
__device__ float g_h[FLATN];       // x@W buffer (reused for both layers)
__device__ float g_e1[FLATN];      // layer-1 output
__device__ int   g_degi[N_NODES];  // int degree histogram (edges only)
__device__ float g_dinv[N_NODES];
__device__ int   g_rowptr[N_NODES + 1];
__device__ int   g_cursor[N_NODES];
__device__ int   g_src[N_EDGES];   // CSR: source node per (target-sorted) edge
__device__ float g_acc[HID];       // fc1 partial-sum accumulator

// ---------------- prep: zero degree histogram -------------------------------
__global__ void k_prep() {
    int i = blockIdx.x * blockDim.x + threadIdx.x;
    if (i < N_NODES) g_degi[i] = 0;
}

// ---------------- degree histogram over edge targets (4 edges/thread) -------
__global__ void k_deg(const int* __restrict__ col) {
    int t = blockIdx.x * blockDim.x + threadIdx.x;
    int4 c = __ldg((const int4*)col + t);
    atomicAdd(&g_degi[c.x], 1);
    atomicAdd(&g_degi[c.y], 1);
    atomicAdd(&g_degi[c.z], 1);
    atomicAdd(&g_degi[c.w], 1);
}

// ---------------- single-block scan: rowptr, cursor, dinv, acc=0 ------------
__global__ void __launch_bounds__(1024) k_scan() {
    const int t = threadIdx.x;
    int v[8];
    int s = 0;
    #pragma unroll
    for (int i = 0; i < 8; i++) {
        int d = g_degi[t * 8 + i];
        v[i] = s;
        s += d;
    }
    int lane = t & 31, warp = t >> 5;
    int inc = s;
    #pragma unroll
    for (int o = 1; o < 32; o <<= 1) {
        int n = __shfl_up_sync(0xFFFFFFFFu, inc, o);
        if (lane >= o) inc += n;
    }
    __shared__ int wsum[32];
    if (lane == 31) wsum[warp] = inc;
    __syncthreads();
    if (warp == 0) {
        int w = wsum[lane];
        #pragma unroll
        for (int o = 1; o < 32; o <<= 1) {
            int n = __shfl_up_sync(0xFFFFFFFFu, w, o);
            if (lane >= o) w += n;
        }
        wsum[lane] = w;
    }
    __syncthreads();
    int base = inc - s + (warp ? wsum[warp - 1] : 0);
    #pragma unroll
    for (int i = 0; i < 8; i++) {
        int p = base + v[i];
        g_rowptr[t * 8 + i] = p;
        g_cursor[t * 8 + i] = p;
    }
    if (t == 1023) g_rowptr[N_NODES] = N_EDGES;
    #pragma unroll
    for (int i = 0; i < 8; i++) {
        int n = t * 8 + i;
        g_dinv[n] = rsqrtf((float)(g_degi[n] + 1));
    }
    if (t < HID) g_acc[t] = 0.f;
}

// ---------------- CSR fill (4 edges/thread) ---------------------------------
__global__ void k_fill(const int* __restrict__ row, const int* __restrict__ col) {
    int t = blockIdx.x * blockDim.x + threadIdx.x;
    int4 c = __ldg((const int4*)col + t);
    int4 r = __ldg((const int4*)row + t);
    int p0 = atomicAdd(&g_cursor[c.x], 1);
    int p1 = atomicAdd(&g_cursor[c.y], 1);
    int p2 = atomicAdd(&g_cursor[c.z], 1);
    int p3 = atomicAdd(&g_cursor[c.w], 1);
    g_src[p0] = r.x;
    g_src[p1] = r.y;
    g_src[p2] = r.z;
    g_src[p3] = r.w;
}

// ---------------- GEMM: out[8192,128] = A[8192,128] @ W[128,128] ------------
#define GBM 32
#define WPITCH 132
__global__ void __launch_bounds__(256, 2) k_gemm(const float* __restrict__ A,
                                                 const float* __restrict__ W,
                                                 float* __restrict__ out) {
    extern __shared__ float smem[];
    float* Ws = smem;                       // [128][WPITCH]
    float* As = smem + 128 * WPITCH;        // [GBM][WPITCH]
    const int tid = threadIdx.x;

    #pragma unroll
    for (int i = tid; i < 128 * 32; i += 256) {
        int k = i >> 5, c4 = i & 31;
        *(float4*)&Ws[k * WPITCH + c4 * 4] = __ldg((const float4*)(W + k * HID) + c4);
    }
    const float* Ab = A + (size_t)blockIdx.x * GBM * HID;
    #pragma unroll
    for (int i = tid; i < GBM * 32; i += 256) {
        int r = i >> 5, c4 = i & 31;
        *(float4*)&As[r * WPITCH + c4 * 4] = __ldg((const float4*)(Ab + r * HID) + c4);
    }
    __syncthreads();

    const int tx = tid & 31;
    const int ty = tid >> 5;
    float acc[4][4];
    #pragma unroll
    for (int i = 0; i < 4; i++)
        #pragma unroll
        for (int j = 0; j < 4; j++) acc[i][j] = 0.f;

    const float* As0 = &As[(ty * 4 + 0) * WPITCH];
    const float* As1 = &As[(ty * 4 + 1) * WPITCH];
    const float* As2 = &As[(ty * 4 + 2) * WPITCH];
    const float* As3 = &As[(ty * 4 + 3) * WPITCH];

    #pragma unroll 8
    for (int k = 0; k < 128; k++) {
        float4 wv = *(const float4*)&Ws[k * WPITCH + tx * 4];
        float a0 = As0[k], a1 = As1[k], a2 = As2[k], a3 = As3[k];
        acc[0][0] += a0 * wv.x; acc[0][1] += a0 * wv.y; acc[0][2] += a0 * wv.z; acc[0][3] += a0 * wv.w;
        acc[1][0] += a1 * wv.x; acc[1][1] += a1 * wv.y; acc[1][2] += a1 * wv.z; acc[1][3] += a1 * wv.w;
        acc[2][0] += a2 * wv.x; acc[2][1] += a2 * wv.y; acc[2][2] += a2 * wv.z; acc[2][3] += a2 * wv.w;
        acc[3][0] += a3 * wv.x; acc[3][1] += a3 * wv.y; acc[3][2] += a3 * wv.z; acc[3][3] += a3 * wv.w;
    }
    #pragma unroll
    for (int i = 0; i < 4; i++) {
        float4 v = make_float4(acc[i][0], acc[i][1], acc[i][2], acc[i][3]);
        *(float4*)(out + (size_t)(blockIdx.x * GBM + ty * 4 + i) * HID + tx * 4) = v;
    }
}
#define GEMM_SMEM ((128 * WPITCH + GBM * WPITCH) * 4)

// ---------------- pipelined neighbor accumulation (device helper) -----------
// Accumulates sum over CSR range [start,end) of dinv[src]*dc * h[src][lane*4..+3]
__device__ __forceinline__ float4 gather_accum(const float* __restrict__ h,
                                               int start, int end, float dc,
                                               int lane) {
    float4 acc0 = make_float4(0.f, 0.f, 0.f, 0.f);
    float4 acc1 = make_float4(0.f, 0.f, 0.f, 0.f);
    for (int j = start; j < end; j += 32) {
        int n = min(32, end - j);
        int s = 0; float dv = 0.f;
        if (lane < n) { s = __ldg(g_src + j + lane); dv = g_dinv[s]; }
        int k = 0;
        for (; k + 4 <= n; k += 4) {
            int s0 = __shfl_sync(0xFFFFFFFFu, s, k + 0);
            int s1 = __shfl_sync(0xFFFFFFFFu, s, k + 1);
            int s2 = __shfl_sync(0xFFFFFFFFu, s, k + 2);
            int s3 = __shfl_sync(0xFFFFFFFFu, s, k + 3);
            float n0 = __shfl_sync(0xFFFFFFFFu, dv, k + 0) * dc;
            float n1 = __shfl_sync(0xFFFFFFFFu, dv, k + 1) * dc;
            float n2 = __shfl_sync(0xFFFFFFFFu, dv, k + 2) * dc;
            float n3 = __shfl_sync(0xFFFFFFFFu, dv, k + 3) * dc;
            float4 v0 = __ldg((const float4*)(h + (size_t)s0 * HID) + lane);
            float4 v1 = __ldg((const float4*)(h + (size_t)s1 * HID) + lane);
            float4 v2 = __ldg((const float4*)(h + (size_t)s2 * HID) + lane);
            float4 v3 = __ldg((const float4*)(h + (size_t)s3 * HID) + lane);
            acc0.x += n0 * v0.x; acc0.y += n0 * v0.y; acc0.z += n0 * v0.z; acc0.w += n0 * v0.w;
            acc1.x += n1 * v1.x; acc1.y += n1 * v1.y; acc1.z += n1 * v1.z; acc1.w += n1 * v1.w;
            acc0.x += n2 * v2.x; acc0.y += n2 * v2.y; acc0.z += n2 * v2.z; acc0.w += n2 * v2.w;
            acc1.x += n3 * v3.x; acc1.y += n3 * v3.y; acc1.z += n3 * v3.z; acc1.w += n3 * v3.w;
        }
        for (; k < n; k++) {
            int src   = __shfl_sync(0xFFFFFFFFu, s, k);
            float nrm = __shfl_sync(0xFFFFFFFFu, dv, k) * dc;
            float4 v  = __ldg((const float4*)(h + (size_t)src * HID) + lane);
            acc0.x += nrm * v.x; acc0.y += nrm * v.y; acc0.z += nrm * v.z; acc0.w += nrm * v.w;
        }
    }
    acc0.x += acc1.x; acc0.y += acc1.y; acc0.z += acc1.z; acc0.w += acc1.w;
    return acc0;
}

// ---------------- gather (layer 1): e1[c] = relu(sum + self + bias) ---------
__global__ void __launch_bounds__(256) k_gather(const float* __restrict__ h,
                                                const float* __restrict__ b,
                                                float* __restrict__ out) {
    const int gtid = blockIdx.x * blockDim.x + threadIdx.x;
    const int node = gtid >> 5;
    const int lane = gtid & 31;
    if (node >= N_NODES) return;
    const float dc = g_dinv[node];
    float4 acc = gather_accum(h, g_rowptr[node], g_rowptr[node + 1], dc, lane);

    float nn = dc * dc;
    float4 hv = __ldg((const float4*)(h + (size_t)node * HID) + lane);
    float4 bv = __ldg((const float4*)b + lane);
    acc.x = fmaxf(acc.x + nn * hv.x + bv.x, 0.f);
    acc.y = fmaxf(acc.y + nn * hv.y + bv.y, 0.f);
    acc.z = fmaxf(acc.z + nn * hv.z + bv.z, 0.f);
    acc.w = fmaxf(acc.w + nn * hv.w + bv.w, 0.f);
    *(float4*)(out + (size_t)node * HID + lane * 4) = acc;
}

// ---------------- gather (layer 2) fused with fc1 ---------------------------
__global__ void __launch_bounds__(256) k_gather_fc1(const float* __restrict__ h,
                                                    const float* __restrict__ b,
                                                    const float* __restrict__ fc1_w) {
    __shared__ float fs[8][HID];
    const int gtid = blockIdx.x * blockDim.x + threadIdx.x;
    const int node = gtid >> 5;
    const int lane = gtid & 31;
    const int warp = threadIdx.x >> 5;
    if (node >= N_NODES) return;
    const float dc = g_dinv[node];
    float4 acc = gather_accum(h, g_rowptr[node], g_rowptr[node + 1], dc, lane);

    float nn = dc * dc;
    float4 hv = __ldg((const float4*)(h + (size_t)node * HID) + lane);
    float4 bv = __ldg((const float4*)b + lane);
    acc.x += nn * hv.x + bv.x;
    acc.y += nn * hv.y + bv.y;
    acc.z += nn * hv.z + bv.z;
    acc.w += nn * hv.w + bv.w;
    *(float4*)&fs[warp][lane * 4] = acc;
    __syncwarp();

    // Phase 2: fc1 partial for this node's 128 flat values.
    // __ldcs: evict-first streaming — don't thrash L2 copy of h.
    const float* Wb = fc1_w + (size_t)node * HID * HID;
    float4 p = make_float4(0.f, 0.f, 0.f, 0.f);
    #pragma unroll 8
    for (int j = 0; j < HID; j++) {
        float fj = fs[warp][j];
        float4 w = __ldcs((const float4*)(Wb + (size_t)j * HID) + lane);
        p.x += fj * w.x; p.y += fj * w.y; p.z += fj * w.z; p.w += fj * w.w;
    }
    float* dst = &g_acc[lane * 4];
    asm volatile("red.global.add.v4.f32 [%0], {%1, %2, %3, %4};"
                 :: "l"(dst), "f"(p.x), "f"(p.y), "f"(p.z), "f"(p.w)
                 : "memory");
}

// ---------------- tail: relu(fc1) -> fc2+relu -> fc3 -> scalar --------------
__global__ void k_tail(const float* __restrict__ fc1_b,
                       const float* __restrict__ fc2_w,
                       const float* __restrict__ fc2_b,
                       const float* __restrict__ fc3_w,
                       const float* __restrict__ fc3_b,
                       float* __restrict__ out) {
    __shared__ float h1[HID];
    __shared__ float red[4];
    int tid = threadIdx.x;
    h1[tid] = fmaxf(g_acc[tid] + fc1_b[tid], 0.f);
    __syncthreads();
    float s = 0.f;
    #pragma unroll 8
    for (int k = 0; k < HID; k++) s += h1[k] * fc2_w[k * HID + tid];
    float h2 = fmaxf(s + fc2_b[tid], 0.f);
    float p = h2 * fc3_w[tid];
    #pragma unroll
    for (int o = 16; o; o >>= 1) p += __shfl_xor_sync(0xFFFFFFFFu, p, o);
    if ((tid & 31) == 0) red[tid >> 5] = p;
    __syncthreads();
    if (tid == 0) out[0] = red[0] + red[1] + red[2] + red[3] + fc3_b[0];
}

// ---------------- launch ----------------------------------------------------
extern "C" void kernel_launch(void* const* d_in, const int* in_sizes, int n_in,
                              void* d_out, int out_size) {
    const float* x      = (const float*)d_in[0];
    const int*   ei     = (const int*)d_in[1];     // [2, N_EDGES] row-major
    const float* W1     = (const float*)d_in[2];
    const float* b1     = (const float*)d_in[3];
    const float* W2     = (const float*)d_in[4];
    const float* b2     = (const float*)d_in[5];
    const float* fc1_w  = (const float*)d_in[6];
    const float* fc1_b  = (const float*)d_in[7];
    const float* fc2_w  = (const float*)d_in[8];
    const float* fc2_b  = (const float*)d_in[9];
    const float* fc3_w  = (const float*)d_in[10];
    const float* fc3_b  = (const float*)d_in[11];
    float* out = (float*)d_out;

    const int* row = ei;               // sources
    const int* colv = ei + N_EDGES;    // targets

    float *p_h, *p_e1;
    cudaGetSymbolAddress((void**)&p_h,  g_h);
    cudaGetSymbolAddress((void**)&p_e1, g_e1);

    cudaFuncSetAttribute(k_gemm, cudaFuncAttributeMaxDynamicSharedMemorySize, GEMM_SMEM);

    // Graph preprocessing: CSR by target + dinv
    k_prep<<<N_NODES / 256, 256>>>();
    k_deg<<<N_EDGES / 4 / 256, 256>>>(colv);
    k_scan<<<1, 1024>>>();
    k_fill<<<N_EDGES / 4 / 256, 256>>>(row, colv);

    // Layer 1
    k_gemm<<<N_NODES / GBM, 256, GEMM_SMEM>>>(x, W1, p_h);
    k_gather<<<(N_NODES * 32) / 256, 256>>>(p_h, b1, p_e1);

    // Layer 2 + fc1 fused
    k_gemm<<<N_NODES / GBM, 256, GEMM_SMEM>>>(p_e1, W2, p_h);
    k_gather_fc1<<<(N_NODES * 32) / 256, 256>>>(p_h, b2, fc1_w);

    // MLP tail
    k_tail<<<1, 128>>>(fc1_b, fc2_w, fc2_b, fc3_w, fc3_b, out);
}

// round 5
// speedup vs baseline: 2.0903x; 1.1241x over previous
#include <cuda_runtime.h>
#include <cstddef>

#define N_NODES 8192
#define N_EDGES 262144
#define HID 128
#define FLATN (N_NODES * HID)   // 1048576

// ---------------- scratch (device globals) ----------------------------------
__device__ float g_h[FLATN];       // x@W buffer (reused for both layers)
__device__ float g_e1[FLATN];      // layer-1 output
__device__ int   g_degi[N_NODES];  // int degree histogram (edges only)
__device__ float g_dinv[N_NODES];
__device__ int   g_rowptr[N_NODES + 1];
__device__ int   g_cursor[N_NODES];
__device__ int   g_src[N_EDGES];   // CSR: source node per (target-sorted) edge
__device__ float g_acc[HID];       // fc1 partial-sum accumulator

// ---------------- prep: zero degree histogram -------------------------------
__global__ void k_prep() {
    int i = blockIdx.x * blockDim.x + threadIdx.x;
    if (i < N_NODES) g_degi[i] = 0;
}

// ---------------- degree histogram over edge targets (2 edges/thread) -------
__global__ void k_deg(const int* __restrict__ col) {
    int t = blockIdx.x * blockDim.x + threadIdx.x;
    int2 c = __ldg((const int2*)col + t);
    atomicAdd(&g_degi[c.x], 1);
    atomicAdd(&g_degi[c.y], 1);
}

// ---------------- single-block scan: rowptr, cursor, dinv, acc=0 ------------
__global__ void __launch_bounds__(1024) k_scan() {
    const int t = threadIdx.x;
    int v[8];
    int s = 0;
    #pragma unroll
    for (int i = 0; i < 8; i++) {
        int d = g_degi[t * 8 + i];
        v[i] = s;
        s += d;
    }
    int lane = t & 31, warp = t >> 5;
    int inc = s;
    #pragma unroll
    for (int o = 1; o < 32; o <<= 1) {
        int n = __shfl_up_sync(0xFFFFFFFFu, inc, o);
        if (lane >= o) inc += n;
    }
    __shared__ int wsum[32];
    if (lane == 31) wsum[warp] = inc;
    __syncthreads();
    if (warp == 0) {
        int w = wsum[lane];
        #pragma unroll
        for (int o = 1; o < 32; o <<= 1) {
            int n = __shfl_up_sync(0xFFFFFFFFu, w, o);
            if (lane >= o) w += n;
        }
        wsum[lane] = w;
    }
    __syncthreads();
    int base = inc - s + (warp ? wsum[warp - 1] : 0);
    #pragma unroll
    for (int i = 0; i < 8; i++) {
        int p = base + v[i];
        g_rowptr[t * 8 + i] = p;
        g_cursor[t * 8 + i] = p;
    }
    if (t == 1023) g_rowptr[N_NODES] = N_EDGES;
    #pragma unroll
    for (int i = 0; i < 8; i++) {
        int n = t * 8 + i;
        g_dinv[n] = rsqrtf((float)(g_degi[n] + 1));
    }
    if (t < HID) g_acc[t] = 0.f;
}

// ---------------- CSR fill (2 edges/thread) ---------------------------------
__global__ void k_fill(const int* __restrict__ row, const int* __restrict__ col) {
    int t = blockIdx.x * blockDim.x + threadIdx.x;
    int2 c = __ldg((const int2*)col + t);
    int2 r = __ldg((const int2*)row + t);
    int p0 = atomicAdd(&g_cursor[c.x], 1);
    int p1 = atomicAdd(&g_cursor[c.y], 1);
    g_src[p0] = r.x;
    g_src[p1] = r.y;
}

// ---------------- GEMM: out[8192,128] = A[8192,128] @ W[128,128] ------------
#define GBM 32
#define WPITCH 132
__global__ void __launch_bounds__(256, 2) k_gemm(const float* __restrict__ A,
                                                 const float* __restrict__ W,
                                                 float* __restrict__ out) {
    extern __shared__ float smem[];
    float* Ws = smem;                       // [128][WPITCH]
    float* As = smem + 128 * WPITCH;        // [GBM][WPITCH]
    const int tid = threadIdx.x;

    #pragma unroll
    for (int i = tid; i < 128 * 32; i += 256) {
        int k = i >> 5, c4 = i & 31;
        *(float4*)&Ws[k * WPITCH + c4 * 4] = __ldg((const float4*)(W + k * HID) + c4);
    }
    const float* Ab = A + (size_t)blockIdx.x * GBM * HID;
    #pragma unroll
    for (int i = tid; i < GBM * 32; i += 256) {
        int r = i >> 5, c4 = i & 31;
        *(float4*)&As[r * WPITCH + c4 * 4] = __ldg((const float4*)(Ab + r * HID) + c4);
    }
    __syncthreads();

    const int tx = tid & 31;
    const int ty = tid >> 5;
    float acc[4][4];
    #pragma unroll
    for (int i = 0; i < 4; i++)
        #pragma unroll
        for (int j = 0; j < 4; j++) acc[i][j] = 0.f;

    const float* As0 = &As[(ty * 4 + 0) * WPITCH];
    const float* As1 = &As[(ty * 4 + 1) * WPITCH];
    const float* As2 = &As[(ty * 4 + 2) * WPITCH];
    const float* As3 = &As[(ty * 4 + 3) * WPITCH];

    #pragma unroll 8
    for (int k = 0; k < 128; k++) {
        float4 wv = *(const float4*)&Ws[k * WPITCH + tx * 4];
        float a0 = As0[k], a1 = As1[k], a2 = As2[k], a3 = As3[k];
        acc[0][0] += a0 * wv.x; acc[0][1] += a0 * wv.y; acc[0][2] += a0 * wv.z; acc[0][3] += a0 * wv.w;
        acc[1][0] += a1 * wv.x; acc[1][1] += a1 * wv.y; acc[1][2] += a1 * wv.z; acc[1][3] += a1 * wv.w;
        acc[2][0] += a2 * wv.x; acc[2][1] += a2 * wv.y; acc[2][2] += a2 * wv.z; acc[2][3] += a2 * wv.w;
        acc[3][0] += a3 * wv.x; acc[3][1] += a3 * wv.y; acc[3][2] += a3 * wv.z; acc[3][3] += a3 * wv.w;
    }
    #pragma unroll
    for (int i = 0; i < 4; i++) {
        float4 v = make_float4(acc[i][0], acc[i][1], acc[i][2], acc[i][3]);
        *(float4*)(out + (size_t)(blockIdx.x * GBM + ty * 4 + i) * HID + tx * 4) = v;
    }
}
#define GEMM_SMEM ((128 * WPITCH + GBM * WPITCH) * 4)

// ---------------- block-per-node neighbor accumulation (helper) --------------
// Block = 128 threads, thread = column. Stages (norm, row_offset) in smem,
// zero-padded to a multiple of 8 so the inner loop is a clean unroll-8 of
// independent scalar LDG + FFMA.
__device__ __forceinline__ float gather_blk(const float* __restrict__ h,
                                            int node, int tid,
                                            float* s_nrm, int* s_off,
                                            float dc) {
    const int start = g_rowptr[node];
    const int end   = g_rowptr[node + 1];
    float acc0 = 0.f, acc1 = 0.f;
    for (int j0 = start; j0 < end; j0 += 128) {
        int m  = min(128, end - j0);
        int mp = (m + 7) & ~7;
        if (tid < m) {
            int s = __ldg(g_src + j0 + tid);
            s_nrm[tid] = g_dinv[s] * dc;
            s_off[tid] = s * HID;
        } else if (tid < mp) {
            s_nrm[tid] = 0.f;
            s_off[tid] = 0;
        }
        __syncthreads();
        for (int k = 0; k < mp; k += 8) {
            #pragma unroll
            for (int u = 0; u < 8; u += 2) {
                float n0 = s_nrm[k + u];
                float n1 = s_nrm[k + u + 1];
                float v0 = __ldg(h + s_off[k + u] + tid);
                float v1 = __ldg(h + s_off[k + u + 1] + tid);
                acc0 += n0 * v0;
                acc1 += n1 * v1;
            }
        }
        __syncthreads();
    }
    return acc0 + acc1;
}

// ---------------- gather (layer 1): e1[c] = relu(sum + self + bias) ---------
__global__ void __launch_bounds__(128) k_gather(const float* __restrict__ h,
                                                const float* __restrict__ b,
                                                float* __restrict__ out) {
    __shared__ float s_nrm[128];
    __shared__ int   s_off[128];
    const int node = blockIdx.x;
    const int tid  = threadIdx.x;
    const float dc = g_dinv[node];

    float acc = gather_blk(h, node, tid, s_nrm, s_off, dc);
    acc += dc * dc * __ldg(h + (size_t)node * HID + tid) + __ldg(b + tid);
    out[(size_t)node * HID + tid] = fmaxf(acc, 0.f);
}

// ---------------- gather (layer 2) fused with fc1 ---------------------------
// Phase 1: block computes flat[node][:] into smem.
// Phase 2: 4 warps co-stream the node's 64KB fc1_w slab (warp w: rows w,w+4,..),
//          reduce partials in smem, one red.v4 per block.
__global__ void __launch_bounds__(128) k_gather_fc1(const float* __restrict__ h,
                                                    const float* __restrict__ b,
                                                    const float* __restrict__ fc1_w) {
    __shared__ float s_nrm[128];
    __shared__ int   s_off[128];
    __shared__ float fs[128];
    __shared__ float4 pp[4][32];
    const int node = blockIdx.x;
    const int tid  = threadIdx.x;
    const int lane = tid & 31;
    const int warp = tid >> 5;
    const float dc = g_dinv[node];

    float acc = gather_blk(h, node, tid, s_nrm, s_off, dc);
    acc += dc * dc * __ldg(h + (size_t)node * HID + tid) + __ldg(b + tid);
    fs[tid] = acc;
    __syncthreads();

    // Phase 2: stream the slab. __ldcs: evict-first, don't thrash L2 copy of h.
    const float* Wb = fc1_w + (size_t)node * (HID * HID);
    float4 p = make_float4(0.f, 0.f, 0.f, 0.f);
    #pragma unroll 8
    for (int jj = 0; jj < 32; jj++) {
        int j = jj * 4 + warp;
        float fj = fs[j];
        float4 w = __ldcs((const float4*)(Wb + (size_t)j * HID) + lane);
        p.x += fj * w.x; p.y += fj * w.y; p.z += fj * w.z; p.w += fj * w.w;
    }
    pp[warp][lane] = p;
    __syncthreads();
    if (warp == 0) {
        float4 s0 = pp[0][lane], s1 = pp[1][lane], s2 = pp[2][lane], s3 = pp[3][lane];
        s0.x += s1.x + s2.x + s3.x;
        s0.y += s1.y + s2.y + s3.y;
        s0.z += s1.z + s2.z + s3.z;
        s0.w += s1.w + s2.w + s3.w;
        float* dst = &g_acc[lane * 4];
        asm volatile("red.global.add.v4.f32 [%0], {%1, %2, %3, %4};"
                     :: "l"(dst), "f"(s0.x), "f"(s0.y), "f"(s0.z), "f"(s0.w)
                     : "memory");
    }
}

// ---------------- tail: relu(fc1) -> fc2+relu -> fc3 -> scalar --------------
__global__ void k_tail(const float* __restrict__ fc1_b,
                       const float* __restrict__ fc2_w,
                       const float* __restrict__ fc2_b,
                       const float* __restrict__ fc3_w,
                       const float* __restrict__ fc3_b,
                       float* __restrict__ out) {
    __shared__ float h1[HID];
    __shared__ float red[4];
    int tid = threadIdx.x;
    h1[tid] = fmaxf(g_acc[tid] + fc1_b[tid], 0.f);
    __syncthreads();
    float s = 0.f;
    #pragma unroll 8
    for (int k = 0; k < HID; k++) s += h1[k] * fc2_w[k * HID + tid];
    float h2 = fmaxf(s + fc2_b[tid], 0.f);
    float p = h2 * fc3_w[tid];
    #pragma unroll
    for (int o = 16; o; o >>= 1) p += __shfl_xor_sync(0xFFFFFFFFu, p, o);
    if ((tid & 31) == 0) red[tid >> 5] = p;
    __syncthreads();
    if (tid == 0) out[0] = red[0] + red[1] + red[2] + red[3] + fc3_b[0];
}

// ---------------- launch ----------------------------------------------------
extern "C" void kernel_launch(void* const* d_in, const int* in_sizes, int n_in,
                              void* d_out, int out_size) {
    const float* x      = (const float*)d_in[0];
    const int*   ei     = (const int*)d_in[1];     // [2, N_EDGES] row-major
    const float* W1     = (const float*)d_in[2];
    const float* b1     = (const float*)d_in[3];
    const float* W2     = (const float*)d_in[4];
    const float* b2     = (const float*)d_in[5];
    const float* fc1_w  = (const float*)d_in[6];
    const float* fc1_b  = (const float*)d_in[7];
    const float* fc2_w  = (const float*)d_in[8];
    const float* fc2_b  = (const float*)d_in[9];
    const float* fc3_w  = (const float*)d_in[10];
    const float* fc3_b  = (const float*)d_in[11];
    float* out = (float*)d_out;

    const int* row = ei;               // sources
    const int* colv = ei + N_EDGES;    // targets

    float *p_h, *p_e1;
    cudaGetSymbolAddress((void**)&p_h,  g_h);
    cudaGetSymbolAddress((void**)&p_e1, g_e1);

    cudaFuncSetAttribute(k_gemm, cudaFuncAttributeMaxDynamicSharedMemorySize, GEMM_SMEM);

    // Graph preprocessing: CSR by target + dinv
    k_prep<<<N_NODES / 256, 256>>>();
    k_deg<<<N_EDGES / 2 / 256, 256>>>(colv);
    k_scan<<<1, 1024>>>();
    k_fill<<<N_EDGES / 2 / 256, 256>>>(row, colv);

    // Layer 1
    k_gemm<<<N_NODES / GBM, 256, GEMM_SMEM>>>(x, W1, p_h);
    k_gather<<<N_NODES, 128>>>(p_h, b1, p_e1);

    // Layer 2 + fc1 fused
    k_gemm<<<N_NODES / GBM, 256, GEMM_SMEM>>>(p_e1, W2, p_h);
    k_gather_fc1<<<N_NODES, 128>>>(p_h, b2, fc1_w);

    // MLP tail
    k_tail<<<1, 128>>>(fc1_b, fc2_w, fc2_b, fc3_w, fc3_b, out);
}

// round 6
// speedup vs baseline: 2.2394x; 1.0713x over previous
#include <cuda_runtime.h>
#include <cstddef>

#define N_NODES 8192
#define N_EDGES 262144
#define HID 128
#define FLATN (N_NODES * HID)   // 1048576
#define PF_FLOAT4 (4 * 1024 * 1024)   // 64 MB of fc1_w prefetched to L2

// ---------------- scratch (device globals) ----------------------------------
__device__ float g_h[FLATN];       // x@W buffer (reused for both layers)
__device__ float g_e1[FLATN];      // layer-1 output
__device__ int   g_degi[N_NODES];  // int degree histogram (edges only)
__device__ float g_dinv[N_NODES];
__device__ int   g_rowptr[N_NODES + 1];
__device__ int   g_cursor[N_NODES];
__device__ int   g_src[N_EDGES];   // CSR: source node per (target-sorted) edge
__device__ float g_acc[HID];       // fc1 partial-sum accumulator
__device__ float g_sink;           // prefetch sink (never actually written)

// ---------------- degree histogram over edge targets (2 edges/thread) -------
__global__ void k_deg(const int* __restrict__ col) {
    int t = blockIdx.x * blockDim.x + threadIdx.x;
    int2 c = __ldg((const int2*)col + t);
    atomicAdd(&g_degi[c.x], 1);
    atomicAdd(&g_degi[c.y], 1);
}

// ---------------- single-block scan: rowptr, cursor, dinv, acc=0 ------------
__global__ void __launch_bounds__(1024) k_scan() {
    const int t = threadIdx.x;
    int v[8];
    int s = 0;
    #pragma unroll
    for (int i = 0; i < 8; i++) {
        int d = g_degi[t * 8 + i];
        v[i] = s;
        s += d;
    }
    int lane = t & 31, warp = t >> 5;
    int inc = s;
    #pragma unroll
    for (int o = 1; o < 32; o <<= 1) {
        int n = __shfl_up_sync(0xFFFFFFFFu, inc, o);
        if (lane >= o) inc += n;
    }
    __shared__ int wsum[32];
    if (lane == 31) wsum[warp] = inc;
    __syncthreads();
    if (warp == 0) {
        int w = wsum[lane];
        #pragma unroll
        for (int o = 1; o < 32; o <<= 1) {
            int n = __shfl_up_sync(0xFFFFFFFFu, w, o);
            if (lane >= o) w += n;
        }
        wsum[lane] = w;
    }
    __syncthreads();
    int base = inc - s + (warp ? wsum[warp - 1] : 0);
    #pragma unroll
    for (int i = 0; i < 8; i++) {
        int p = base + v[i];
        g_rowptr[t * 8 + i] = p;
        g_cursor[t * 8 + i] = p;
    }
    if (t == 1023) g_rowptr[N_NODES] = N_EDGES;
    #pragma unroll
    for (int i = 0; i < 8; i++) {
        int n = t * 8 + i;
        g_dinv[n] = rsqrtf((float)(g_degi[n] + 1));
    }
    if (t < HID) g_acc[t] = 0.f;
}

// ---------------- CSR fill (2 edges/thread) ---------------------------------
__global__ void k_fill(const int* __restrict__ row, const int* __restrict__ col) {
    int t = blockIdx.x * blockDim.x + threadIdx.x;
    int2 c = __ldg((const int2*)col + t);
    int2 r = __ldg((const int2*)row + t);
    int p0 = atomicAdd(&g_cursor[c.x], 1);
    int p1 = atomicAdd(&g_cursor[c.y], 1);
    g_src[p0] = r.x;
    g_src[p1] = r.y;
}

// ---------------- L2 warm: touch first 64MB of fc1_w -------------------------
__global__ void __launch_bounds__(256) k_prefetch(const float* __restrict__ w) {
    const float4* p = (const float4*)w;
    int idx = blockIdx.x * blockDim.x + threadIdx.x;
    int stride = gridDim.x * blockDim.x;
    float s = 0.f;
    for (int i = idx; i < PF_FLOAT4; i += stride) {
        float4 v = __ldg(p + i);
        s += v.x + v.y + v.z + v.w;
    }
    // Unprovable-false guard keeps the loads live; never actually stores.
    if (__float_as_uint(s) == 0xDEADBEEFu) g_sink = s;
}

// ---------------- GEMM: out[8192,128] = A[8192,128] @ W[128,128] ------------
#define GBM 32
#define WPITCH 132
__global__ void __launch_bounds__(256, 2) k_gemm(const float* __restrict__ A,
                                                 const float* __restrict__ W,
                                                 float* __restrict__ out) {
    extern __shared__ float smem[];
    float* Ws = smem;                       // [128][WPITCH]
    float* As = smem + 128 * WPITCH;        // [GBM][WPITCH]
    const int tid = threadIdx.x;

    #pragma unroll
    for (int i = tid; i < 128 * 32; i += 256) {
        int k = i >> 5, c4 = i & 31;
        *(float4*)&Ws[k * WPITCH + c4 * 4] = __ldg((const float4*)(W + k * HID) + c4);
    }
    const float* Ab = A + (size_t)blockIdx.x * GBM * HID;
    #pragma unroll
    for (int i = tid; i < GBM * 32; i += 256) {
        int r = i >> 5, c4 = i & 31;
        *(float4*)&As[r * WPITCH + c4 * 4] = __ldg((const float4*)(Ab + r * HID) + c4);
    }
    __syncthreads();

    const int tx = tid & 31;
    const int ty = tid >> 5;
    float acc[4][4];
    #pragma unroll
    for (int i = 0; i < 4; i++)
        #pragma unroll
        for (int j = 0; j < 4; j++) acc[i][j] = 0.f;

    const float* As0 = &As[(ty * 4 + 0) * WPITCH];
    const float* As1 = &As[(ty * 4 + 1) * WPITCH];
    const float* As2 = &As[(ty * 4 + 2) * WPITCH];
    const float* As3 = &As[(ty * 4 + 3) * WPITCH];

    #pragma unroll 8
    for (int k = 0; k < 128; k++) {
        float4 wv = *(const float4*)&Ws[k * WPITCH + tx * 4];
        float a0 = As0[k], a1 = As1[k], a2 = As2[k], a3 = As3[k];
        acc[0][0] += a0 * wv.x; acc[0][1] += a0 * wv.y; acc[0][2] += a0 * wv.z; acc[0][3] += a0 * wv.w;
        acc[1][0] += a1 * wv.x; acc[1][1] += a1 * wv.y; acc[1][2] += a1 * wv.z; acc[1][3] += a1 * wv.w;
        acc[2][0] += a2 * wv.x; acc[2][1] += a2 * wv.y; acc[2][2] += a2 * wv.z; acc[2][3] += a2 * wv.w;
        acc[3][0] += a3 * wv.x; acc[3][1] += a3 * wv.y; acc[3][2] += a3 * wv.z; acc[3][3] += a3 * wv.w;
    }
    #pragma unroll
    for (int i = 0; i < 4; i++) {
        float4 v = make_float4(acc[i][0], acc[i][1], acc[i][2], acc[i][3]);
        *(float4*)(out + (size_t)(blockIdx.x * GBM + ty * 4 + i) * HID + tx * 4) = v;
    }
}
#define GEMM_SMEM ((128 * WPITCH + GBM * WPITCH) * 4)

// ---------------- block-per-node neighbor accumulation (helper) --------------
__device__ __forceinline__ float gather_blk(const float* __restrict__ h,
                                            int node, int tid,
                                            float* s_nrm, int* s_off,
                                            float dc) {
    const int start = g_rowptr[node];
    const int end   = g_rowptr[node + 1];
    float acc0 = 0.f, acc1 = 0.f;
    for (int j0 = start; j0 < end; j0 += 128) {
        int m  = min(128, end - j0);
        int mp = (m + 7) & ~7;
        if (tid < m) {
            int s = __ldg(g_src + j0 + tid);
            s_nrm[tid] = g_dinv[s] * dc;
            s_off[tid] = s * HID;
        } else if (tid < mp) {
            s_nrm[tid] = 0.f;
            s_off[tid] = 0;
        }
        __syncthreads();
        for (int k = 0; k < mp; k += 8) {
            #pragma unroll
            for (int u = 0; u < 8; u += 2) {
                float n0 = s_nrm[k + u];
                float n1 = s_nrm[k + u + 1];
                float v0 = __ldg(h + s_off[k + u] + tid);
                float v1 = __ldg(h + s_off[k + u + 1] + tid);
                acc0 += n0 * v0;
                acc1 += n1 * v1;
            }
        }
        __syncthreads();
    }
    return acc0 + acc1;
}

// ---------------- gather (layer 1): e1[c] = relu(sum + self + bias) ---------
__global__ void __launch_bounds__(128) k_gather(const float* __restrict__ h,
                                                const float* __restrict__ b,
                                                float* __restrict__ out) {
    __shared__ float s_nrm[128];
    __shared__ int   s_off[128];
    const int node = blockIdx.x;
    const int tid  = threadIdx.x;
    const float dc = g_dinv[node];

    float acc = gather_blk(h, node, tid, s_nrm, s_off, dc);
    acc += dc * dc * __ldg(h + (size_t)node * HID + tid) + __ldg(b + tid);
    out[(size_t)node * HID + tid] = fmaxf(acc, 0.f);
}

// ---------------- gather (layer 2) fused with fc1 ---------------------------
__global__ void __launch_bounds__(128) k_gather_fc1(const float* __restrict__ h,
                                                    const float* __restrict__ b,
                                                    const float* __restrict__ fc1_w) {
    __shared__ float s_nrm[128];
    __shared__ int   s_off[128];
    __shared__ float fs[128];
    __shared__ float4 pp[4][32];
    const int node = blockIdx.x;
    const int tid  = threadIdx.x;
    const int lane = tid & 31;
    const int warp = tid >> 5;
    const float dc = g_dinv[node];

    float acc = gather_blk(h, node, tid, s_nrm, s_off, dc);
    acc += dc * dc * __ldg(h + (size_t)node * HID + tid) + __ldg(b + tid);
    fs[tid] = acc;
    __syncthreads();

    // Phase 2: stream the 64KB slab. __ldcs: evict-first streaming.
    const float* Wb = fc1_w + (size_t)node * (HID * HID);
    float4 p = make_float4(0.f, 0.f, 0.f, 0.f);
    #pragma unroll 8
    for (int jj = 0; jj < 32; jj++) {
        int j = jj * 4 + warp;
        float fj = fs[j];
        float4 w = __ldcs((const float4*)(Wb + (size_t)j * HID) + lane);
        p.x += fj * w.x; p.y += fj * w.y; p.z += fj * w.z; p.w += fj * w.w;
    }
    pp[warp][lane] = p;
    __syncthreads();
    if (warp == 0) {
        float4 s0 = pp[0][lane], s1 = pp[1][lane], s2 = pp[2][lane], s3 = pp[3][lane];
        s0.x += s1.x + s2.x + s3.x;
        s0.y += s1.y + s2.y + s3.y;
        s0.z += s1.z + s2.z + s3.z;
        s0.w += s1.w + s2.w + s3.w;
        float* dst = &g_acc[lane * 4];
        asm volatile("red.global.add.v4.f32 [%0], {%1, %2, %3, %4};"
                     :: "l"(dst), "f"(s0.x), "f"(s0.y), "f"(s0.z), "f"(s0.w)
                     : "memory");
    }
}

// ---------------- tail: relu(fc1) -> fc2+relu -> fc3 -> scalar --------------
__global__ void k_tail(const float* __restrict__ fc1_b,
                       const float* __restrict__ fc2_w,
                       const float* __restrict__ fc2_b,
                       const float* __restrict__ fc3_w,
                       const float* __restrict__ fc3_b,
                       float* __restrict__ out) {
    __shared__ float h1[HID];
    __shared__ float red[4];
    int tid = threadIdx.x;
    h1[tid] = fmaxf(g_acc[tid] + fc1_b[tid], 0.f);
    __syncthreads();
    float s = 0.f;
    #pragma unroll 8
    for (int k = 0; k < HID; k++) s += h1[k] * fc2_w[k * HID + tid];
    float h2 = fmaxf(s + fc2_b[tid], 0.f);
    float p = h2 * fc3_w[tid];
    #pragma unroll
    for (int o = 16; o; o >>= 1) p += __shfl_xor_sync(0xFFFFFFFFu, p, o);
    if ((tid & 31) == 0) red[tid >> 5] = p;
    __syncthreads();
    if (tid == 0) out[0] = red[0] + red[1] + red[2] + red[3] + fc3_b[0];
}

// ---------------- launch ----------------------------------------------------
extern "C" void kernel_launch(void* const* d_in, const int* in_sizes, int n_in,
                              void* d_out, int out_size) {
    const float* x      = (const float*)d_in[0];
    const int*   ei     = (const int*)d_in[1];     // [2, N_EDGES] row-major
    const float* W1     = (const float*)d_in[2];
    const float* b1     = (const float*)d_in[3];
    const float* W2     = (const float*)d_in[4];
    const float* b2     = (const float*)d_in[5];
    const float* fc1_w  = (const float*)d_in[6];
    const float* fc1_b  = (const float*)d_in[7];
    const float* fc2_w  = (const float*)d_in[8];
    const float* fc2_b  = (const float*)d_in[9];
    const float* fc3_w  = (const float*)d_in[10];
    const float* fc3_b  = (const float*)d_in[11];
    float* out = (float*)d_out;

    const int* row = ei;               // sources
    const int* colv = ei + N_EDGES;    // targets

    float *p_h, *p_e1;
    int *p_degi;
    cudaGetSymbolAddress((void**)&p_h,    g_h);
    cudaGetSymbolAddress((void**)&p_e1,   g_e1);
    cudaGetSymbolAddress((void**)&p_degi, g_degi);

    cudaFuncSetAttribute(k_gemm, cudaFuncAttributeMaxDynamicSharedMemorySize, GEMM_SMEM);

    // One-time handle creation (host resources only; no device allocation).
    static cudaStream_t s2 = nullptr, s3 = nullptr;
    static cudaEvent_t ev_root = nullptr, ev_pre = nullptr, ev_pf = nullptr;
    if (!s2) {
        cudaStreamCreateWithFlags(&s2, cudaStreamNonBlocking);
        cudaStreamCreateWithFlags(&s3, cudaStreamNonBlocking);
        cudaEventCreateWithFlags(&ev_root, cudaEventDisableTiming);
        cudaEventCreateWithFlags(&ev_pre,  cudaEventDisableTiming);
        cudaEventCreateWithFlags(&ev_pf,   cudaEventDisableTiming);
    }

    // Fork: preproc on s2, fc1_w L2-warm on s3, gemm1 on the main stream.
    cudaEventRecord(ev_root, 0);
    cudaStreamWaitEvent(s2, ev_root, 0);
    cudaStreamWaitEvent(s3, ev_root, 0);

    cudaMemsetAsync(p_degi, 0, N_NODES * sizeof(int), s2);
    k_deg<<<N_EDGES / 2 / 256, 256, 0, s2>>>(colv);
    k_scan<<<1, 1024, 0, s2>>>();
    k_fill<<<N_EDGES / 2 / 256, 256, 0, s2>>>(row, colv);
    cudaEventRecord(ev_pre, s2);

    k_prefetch<<<1024, 256, 0, s3>>>(fc1_w);
    cudaEventRecord(ev_pf, s3);

    k_gemm<<<N_NODES / GBM, 256, GEMM_SMEM>>>(x, W1, p_h);

    // Join preproc before gather1.
    cudaStreamWaitEvent(0, ev_pre, 0);
    k_gather<<<N_NODES, 128>>>(p_h, b1, p_e1);

    k_gemm<<<N_NODES / GBM, 256, GEMM_SMEM>>>(p_e1, W2, p_h);

    // Join prefetch before the fused stream kernel.
    cudaStreamWaitEvent(0, ev_pf, 0);
    k_gather_fc1<<<N_NODES, 128>>>(p_h, b2, fc1_w);

    k_tail<<<1, 128>>>(fc1_b, fc2_w, fc2_b, fc3_w, fc3_b, out);
}